// round 2
// baseline (speedup 1.0000x reference)
#include <cuda_runtime.h>
#include <math.h>

#define NNODES 4096
#define NEDGES 65536
#define HD     256

// ---------------- scratch (static device memory; no allocs allowed) ----------------
__device__ float g_h   [NNODES * HD];        // current node features
__device__ float g_xw  [NNODES * HD];        // gcn x@W^T
__device__ float g_agg [NNODES * HD];        // gcn aggregation (later: h1 + gcn_b + 2x)
__device__ float g_qkv [NNODES * 3 * HD];    // attention qkv
__device__ float g_attn[NNODES * HD];        // attention output (pre out-proj)
__device__ float g_out [NNODES * HD];        // h1 + h2
__device__ float g_ffn [NNODES * 2 * HD];    // ffn hidden
__device__ float g_z   [NNODES * HD];        // final mlp hidden
__device__ float g_dinv[NNODES];
__device__ float g_deg [NNODES];

// ---------------- generic tiled SGEMM ----------------
// C[M,N] = relu?( alpha * A @ op(B) + bias + res )
// TRANSB=true : B is [N,K] row-major (weights), C = A B^T   (NT)
// TRANSB=false: B is [K,N] row-major,           C = A B     (NN)
// ATOMIC=true : epilogue atomicAdd (split-K over gridDim.z); bias/res/relu must be off.
// BM=BN=64, BK=16, 128 threads, 8x4 per-thread tile.
template<bool TRANSB, bool ATOMIC>
__global__ __launch_bounds__(128)
void gemm_k(const float* __restrict__ A, int lda,
            const float* __restrict__ B, int ldb,
            float* __restrict__ C, int ldc,
            int Kchunk, float alpha,
            const float* __restrict__ bias,
            const float* __restrict__ res, int ldr,
            int relu)
{
    __shared__ float As[16][68];
    __shared__ float Bs[16][68];

    const int bm = blockIdx.y * 64;
    const int bn = blockIdx.x * 64;
    const int t  = threadIdx.x;
    const int tx = t & 15;        // 16 groups of 4 cols
    const int ty = t >> 4;        // 8 groups of 8 rows
    const int lr = t >> 1;        // load row 0..63
    const int lh = (t & 1) * 8;   // load col-half offset (0 or 8)

    float acc[8][4];
#pragma unroll
    for (int i = 0; i < 8; i++)
#pragma unroll
        for (int j = 0; j < 4; j++) acc[i][j] = 0.f;

    const int kbeg = blockIdx.z * Kchunk;
    const int kend = kbeg + Kchunk;

    for (int k0 = kbeg; k0 < kend; k0 += 16) {
        // load A tile [64 x 16], store transposed As[k][m]
        {
            const float* ap = A + (size_t)(bm + lr) * lda + k0 + lh;
            float4 v0 = *(const float4*)(ap);
            float4 v1 = *(const float4*)(ap + 4);
            As[lh + 0][lr] = v0.x; As[lh + 1][lr] = v0.y;
            As[lh + 2][lr] = v0.z; As[lh + 3][lr] = v0.w;
            As[lh + 4][lr] = v1.x; As[lh + 5][lr] = v1.y;
            As[lh + 6][lr] = v1.z; As[lh + 7][lr] = v1.w;
        }
        if (TRANSB) {
            const float* bp = B + (size_t)(bn + lr) * ldb + k0 + lh;
            float4 v0 = *(const float4*)(bp);
            float4 v1 = *(const float4*)(bp + 4);
            Bs[lh + 0][lr] = v0.x; Bs[lh + 1][lr] = v0.y;
            Bs[lh + 2][lr] = v0.z; Bs[lh + 3][lr] = v0.w;
            Bs[lh + 4][lr] = v1.x; Bs[lh + 5][lr] = v1.y;
            Bs[lh + 6][lr] = v1.z; Bs[lh + 7][lr] = v1.w;
        } else {
            const int kr = t >> 3;          // 0..15
            const int cc = (t & 7) * 8;     // 0..56
            const float* bp = B + (size_t)(k0 + kr) * ldb + bn + cc;
            float4 w0 = *(const float4*)(bp);
            float4 w1 = *(const float4*)(bp + 4);
            *(float4*)&Bs[kr][cc]     = w0;
            *(float4*)&Bs[kr][cc + 4] = w1;
        }
        __syncthreads();

#pragma unroll
        for (int kk = 0; kk < 16; kk++) {
            float a[8], b[4];
            *(float4*)(a)     = *(const float4*)&As[kk][ty * 8];
            *(float4*)(a + 4) = *(const float4*)&As[kk][ty * 8 + 4];
            *(float4*)(b)     = *(const float4*)&Bs[kk][tx * 4];
#pragma unroll
            for (int i = 0; i < 8; i++)
#pragma unroll
                for (int j = 0; j < 4; j++)
                    acc[i][j] += a[i] * b[j];
        }
        __syncthreads();
    }

    // epilogue
#pragma unroll
    for (int i = 0; i < 8; i++) {
        const int row = bm + ty * 8 + i;
        const int col = bn + tx * 4;
        if (ATOMIC) {
#pragma unroll
            for (int j = 0; j < 4; j++)
                atomicAdd(&C[(size_t)row * ldc + col + j], acc[i][j] * alpha);
        } else {
            float4 v;
            v.x = acc[i][0] * alpha; v.y = acc[i][1] * alpha;
            v.z = acc[i][2] * alpha; v.w = acc[i][3] * alpha;
            if (bias) {
                const float4 bv = *(const float4*)(bias + col);
                v.x += bv.x; v.y += bv.y; v.z += bv.z; v.w += bv.w;
            }
            if (res) {
                const float4 rv = *(const float4*)(res + (size_t)row * ldr + col);
                v.x += rv.x; v.y += rv.y; v.z += rv.z; v.w += rv.w;
            }
            if (relu) {
                v.x = fmaxf(v.x, 0.f); v.y = fmaxf(v.y, 0.f);
                v.z = fmaxf(v.z, 0.f); v.w = fmaxf(v.w, 0.f);
            }
            *(float4*)(C + (size_t)row * ldc + col) = v;
        }
    }
}

// ---------------- softmax over 4096-wide rows (row staged in SMEM) ----------------
__global__ __launch_bounds__(256)
void softmax_rows(float* __restrict__ S)
{
    __shared__ float buf[4096];
    __shared__ float red[256];
    const int t = threadIdx.x;
    float* p = S + (size_t)blockIdx.x * 4096;

    float m = -3.4e38f;
#pragma unroll
    for (int i = 0; i < 4; i++) {
        const int c = t * 4 + i * 1024;
        float4 v = *(const float4*)(p + c);
        *(float4*)(buf + c) = v;
        m = fmaxf(m, fmaxf(fmaxf(v.x, v.y), fmaxf(v.z, v.w)));
    }
    red[t] = m;
    __syncthreads();
    for (int s = 128; s > 0; s >>= 1) {
        if (t < s) red[t] = fmaxf(red[t], red[t + s]);
        __syncthreads();
    }
    const float M = red[0];
    __syncthreads();

    float sum = 0.f;
#pragma unroll
    for (int i = 0; i < 4; i++) {
        const int c = t * 4 + i * 1024;
        float4 v = *(float4*)(buf + c);
        v.x = __expf(v.x - M); v.y = __expf(v.y - M);
        v.z = __expf(v.z - M); v.w = __expf(v.w - M);
        *(float4*)(buf + c) = v;
        sum += v.x + v.y + v.z + v.w;
    }
    red[t] = sum;
    __syncthreads();
    for (int s = 128; s > 0; s >>= 1) {
        if (t < s) red[t] += red[t + s];
        __syncthreads();
    }
    const float inv = 1.f / red[0];

#pragma unroll
    for (int i = 0; i < 4; i++) {
        const int c = t * 4 + i * 1024;
        float4 v = *(float4*)(buf + c);
        v.x *= inv; v.y *= inv; v.z *= inv; v.w *= inv;
        *(float4*)(p + c) = v;
    }
}

// ---------------- GCN helpers ----------------
__global__ void deg_init_k()
{
    g_deg[blockIdx.x * 256 + threadIdx.x] = 1.0f;   // self-loop
}
__global__ void deg_count_k(const int* __restrict__ ei)
{
    const int e = blockIdx.x * 256 + threadIdx.x;
    atomicAdd(&g_deg[__ldg(ei + NEDGES + e)], 1.0f);   // dst row of edge_index
}
__global__ void dinv_k()
{
    const int i = blockIdx.x * 256 + threadIdx.x;
    g_dinv[i] = rsqrtf(g_deg[i]);
}
__global__ void agg_init_k()
{
    const int idx = blockIdx.x * 256 + threadIdx.x;   // over NNODES*HD
    const int i = idx >> 8;
    const float dv = g_dinv[i];
    g_agg[idx] = dv * dv * g_xw[idx];
}
__global__ void gcn_scatter_k(const int* __restrict__ ei)
{
    const int gid  = blockIdx.x * 256 + threadIdx.x;
    const int e    = gid >> 5;
    const int lane = gid & 31;
    const int s = __ldg(ei + e);
    const int d = __ldg(ei + NEDGES + e);
    const float coef = g_dinv[s] * g_dinv[d];
    const float* xs = g_xw + (size_t)s * HD;
    float* ad = g_agg + (size_t)d * HD;
#pragma unroll
    for (int c = lane; c < HD; c += 32)
        atomicAdd(&ad[c], coef * xs[c]);
}
// agg += gcn_b + 2*x   (prepares "h1 + x + x" for the out-proj epilogue)
__global__ void add_bias_2x_k(const float* __restrict__ b)
{
    const int idx = blockIdx.x * 256 + threadIdx.x;
    g_agg[idx] += b[idx & 255] + 2.0f * g_h[idx];
}
__global__ void zero_attn_k()
{
    g_attn[blockIdx.x * 256 + threadIdx.x] = 0.f;
}

// ---------------- final symmetrization in place ----------------
__global__ __launch_bounds__(1024)
void symmetrize_k(float* __restrict__ D)
{
    if (blockIdx.x < blockIdx.y) return;                       // upper-triangular tile pairs
    if (blockIdx.x == blockIdx.y && threadIdx.x < threadIdx.y) return;
    const int i = blockIdx.y * 32 + threadIdx.y;
    const int j = blockIdx.x * 32 + threadIdx.x;
    const float a = D[(size_t)i * 4096 + j];
    const float b = D[(size_t)j * 4096 + i];
    const float v = 0.5f * (a + b);
    D[(size_t)i * 4096 + j] = v;
    D[(size_t)j * 4096 + i] = v;
}

// ---------------- host-side helpers ----------------
static inline void gemmNT(const float* A, int lda, const float* B, int ldb,
                          float* C, int ldc, int M, int N, int K, float alpha,
                          const float* bias, const float* res, int ldr, int relu)
{
    dim3 grid(N / 64, M / 64, 1);
    gemm_k<true, false><<<grid, 128>>>(A, lda, B, ldb, C, ldc, K, alpha, bias, res, ldr, relu);
}
static inline void gemmNN_split(const float* A, int lda, const float* B, int ldb,
                                float* C, int ldc, int M, int N, int K, int split)
{
    dim3 grid(N / 64, M / 64, split);
    gemm_k<false, true><<<grid, 128>>>(A, lda, B, ldb, C, ldc, K / split, 1.f,
                                       nullptr, nullptr, 0, 0);
}

extern "C" void kernel_launch(void* const* d_in, const int* in_sizes, int n_in,
                              void* d_out, int out_size)
{
    const float* x     = (const float*)d_in[0];
    const int*   ei    = (const int*)  d_in[1];
    const float* pre_w = (const float*)d_in[2];
    const float* pre_b = (const float*)d_in[3];
    const float* P[2][10];
    for (int g = 0; g < 2; g++)
        for (int k = 0; k < 10; k++)
            P[g][k] = (const float*)d_in[4 + g * 10 + k];
    const float* mlp_w1 = (const float*)d_in[24];
    const float* mlp_b1 = (const float*)d_in[25];
    const float* mlp_w2 = (const float*)d_in[26];
    const float* mlp_b2 = (const float*)d_in[27];
    float* out = (float*)d_out;

    float *h, *xw, *agg, *qkv, *attn, *outb, *ffn, *z;
    cudaGetSymbolAddress((void**)&h,    g_h);
    cudaGetSymbolAddress((void**)&xw,   g_xw);
    cudaGetSymbolAddress((void**)&agg,  g_agg);
    cudaGetSymbolAddress((void**)&qkv,  g_qkv);
    cudaGetSymbolAddress((void**)&attn, g_attn);
    cudaGetSymbolAddress((void**)&outb, g_out);
    cudaGetSymbolAddress((void**)&ffn,  g_ffn);
    cudaGetSymbolAddress((void**)&z,    g_z);

    // pre: h = relu(x @ pre_w^T + pre_b)
    gemmNT(x, 128, pre_w, 128, h, HD, NNODES, HD, 128, 1.f, pre_b, nullptr, 0, 1);

    // degrees (same for both GPS blocks)
    deg_init_k<<<NNODES / 256, 256>>>();
    deg_count_k<<<NEDGES / 256, 256>>>(ei);
    dinv_k<<<NNODES / 256, 256>>>();

    for (int g = 0; g < 2; g++) {
        const float* gcn_w = P[g][0]; const float* gcn_b = P[g][1];
        const float* in_w  = P[g][2]; const float* in_b  = P[g][3];
        const float* out_w = P[g][4]; const float* out_b = P[g][5];
        const float* w1    = P[g][6]; const float* b1    = P[g][7];
        const float* w2    = P[g][8]; const float* b2    = P[g][9];

        // GCN: xw = h @ gcn_w^T ; normalized aggregation into agg
        gemmNT(h, HD, gcn_w, HD, xw, HD, NNODES, HD, HD, 1.f, nullptr, nullptr, 0, 0);
        agg_init_k<<<NNODES * HD / 256, 256>>>();
        gcn_scatter_k<<<NEDGES * 32 / 256, 256>>>(ei);
        add_bias_2x_k<<<NNODES * HD / 256, 256>>>(gcn_b);   // agg = gcn-out + gcn_b + 2h

        // attention: qkv = h @ in_w^T + in_b
        gemmNT(h, HD, in_w, HD, qkv, 3 * HD, NNODES, 3 * HD, HD, 1.f, in_b, nullptr, 0, 0);

        zero_attn_k<<<NNODES * HD / 256, 256>>>();
        for (int hd = 0; hd < 4; hd++) {
            // S = (q * d^-1/2) @ k^T  -> scratch in d_out
            gemmNT(qkv + hd * 64, 3 * HD, qkv + HD + hd * 64, 3 * HD,
                   out, 4096, NNODES, NNODES, 64, 0.125f, nullptr, nullptr, 0, 0);
            softmax_rows<<<NNODES, 256>>>(out);
            // O_head = S @ v  (NN, split-K=8, atomic accumulate)
            gemmNN_split(out, 4096, qkv + 2 * HD + hd * 64, 3 * HD,
                         attn + hd * 64, HD, NNODES, 64, NNODES, 8);
        }

        // out = attn @ out_w^T + out_b + (agg)   [agg already holds h1 + 2h]
        gemmNT(attn, HD, out_w, HD, outb, HD, NNODES, HD, HD, 1.f, out_b, agg, HD, 0);

        // FFN + residual + outer relu -> h (next block input)
        gemmNT(outb, HD, w1, HD, ffn, 2 * HD, NNODES, 2 * HD, HD, 1.f, b1, nullptr, 0, 1);
        gemmNT(ffn, 2 * HD, w2, 2 * HD, h, HD, NNODES, HD, 2 * HD, 1.f, b2, outb, HD, 1);
    }

    // final: z = relu(h @ mlp_w1^T + b1); delta = z @ mlp_w2^T + b2; sym in-place
    gemmNT(h, HD, mlp_w1, HD, z, HD, NNODES, HD, HD, 1.f, mlp_b1, nullptr, 0, 1);
    gemmNT(z, HD, mlp_w2, HD, out, 4096, NNODES, 4096, HD, 1.f, mlp_b2, nullptr, 0, 0);
    symmetrize_k<<<dim3(128, 128), dim3(32, 32)>>>(out);
}

// round 3
// speedup vs baseline: 2.5600x; 2.5600x over previous
#include <cuda_runtime.h>
#include <math.h>

#define NNODES 4096
#define NEDGES 65536
#define HD     256

// ---------------- scratch (static device memory; no allocs allowed) ----------------
__device__ float g_h   [NNODES * HD];
__device__ float g_xw  [NNODES * HD];
__device__ float g_agg [NNODES * HD];
__device__ float g_qkv [NNODES * 3 * HD];
__device__ float g_attn[NNODES * HD];
__device__ float g_out [NNODES * HD];
__device__ float g_ffn [NNODES * 2 * HD];
__device__ float g_z   [NNODES * HD];
__device__ float g_dinv[NNODES];
__device__ float g_deg [NNODES];

__device__ __forceinline__ float f2tf32(float x)
{
    asm("cvt.rna.tf32.f32 %0, %1;" : "=f"(x) : "f"(x));
    return x;
}

// ---------------- tf32 tensor-core GEMM ----------------
// C[M,N] = relu?( alpha * A @ op(B) + bias + res )
// TRANSB=true : B is [N,K] row-major (weights), C = A B^T
// TRANSB=false: B is [K,N] row-major,           C = A B
// ATOMIC=true : epilogue atomicAdd (split-K over gridDim.z)
// BM=128, BN=64, BK=32. 256 threads = 8 warps (4 x 2), warp tile 32x32.
template<bool TRANSB, bool ATOMIC>
__global__ __launch_bounds__(256)
void gemm_tc(const float* __restrict__ A, int lda,
             const float* __restrict__ B, int ldb,
             float* __restrict__ C, int ldc,
             int Kchunk, float alpha,
             const float* __restrict__ bias,
             const float* __restrict__ res, int ldr,
             int relu)
{
    __shared__ float As[32][136];   // [k][m], stride 136 ≡ 8 mod 32 (conflict-free frags)
    __shared__ float Bs[32][72];    // [k][n], stride 72  ≡ 8 mod 32

    const int bm = blockIdx.y * 128;
    const int bn = blockIdx.x * 64;
    const int t  = threadIdx.x;
    const int w  = t >> 5;
    const int lane = t & 31;
    const int qr = lane >> 2;       // 0..7
    const int qc = lane & 3;        // 0..3
    const int wm = (w & 3) * 32;    // warp row offset in tile
    const int wn = (w >> 2) * 32;   // warp col offset in tile

    float acc[2][4][4];
#pragma unroll
    for (int i = 0; i < 2; i++)
#pragma unroll
        for (int j = 0; j < 4; j++)
#pragma unroll
            for (int r = 0; r < 4; r++) acc[i][j][r] = 0.f;

    const int kbeg = blockIdx.z * Kchunk;
    const int kend = kbeg + Kchunk;

    for (int k0 = kbeg; k0 < kend; k0 += 32) {
        // ---- load A tile [128 x 32] -> As[k][m] (tf32-rounded) ----
        {
            const int r  = t >> 1;           // 0..127
            const int ch = (t & 1) * 16;     // col half
            const float* ap = A + (size_t)(bm + r) * lda + k0 + ch;
#pragma unroll
            for (int q = 0; q < 4; q++) {
                float4 v = *(const float4*)(ap + q * 4);
                As[ch + q * 4 + 0][r] = f2tf32(v.x);
                As[ch + q * 4 + 1][r] = f2tf32(v.y);
                As[ch + q * 4 + 2][r] = f2tf32(v.z);
                As[ch + q * 4 + 3][r] = f2tf32(v.w);
            }
        }
        // ---- load B tile -> Bs[k][n] ----
        if (TRANSB) {
            const int r  = t >> 2;           // 0..63  (row of B = n)
            const int ch = (t & 3) * 8;      // k offset
            const float* bp = B + (size_t)(bn + r) * ldb + k0 + ch;
            float4 v0 = *(const float4*)(bp);
            float4 v1 = *(const float4*)(bp + 4);
            Bs[ch + 0][r] = f2tf32(v0.x); Bs[ch + 1][r] = f2tf32(v0.y);
            Bs[ch + 2][r] = f2tf32(v0.z); Bs[ch + 3][r] = f2tf32(v0.w);
            Bs[ch + 4][r] = f2tf32(v1.x); Bs[ch + 5][r] = f2tf32(v1.y);
            Bs[ch + 6][r] = f2tf32(v1.z); Bs[ch + 7][r] = f2tf32(v1.w);
        } else {
            const int kr = t >> 3;           // 0..31
            const int cc = (t & 7) * 8;      // 0..56
            const float* bp = B + (size_t)(k0 + kr) * ldb + bn + cc;
            float4 v0 = *(const float4*)(bp);
            float4 v1 = *(const float4*)(bp + 4);
            Bs[kr][cc + 0] = f2tf32(v0.x); Bs[kr][cc + 1] = f2tf32(v0.y);
            Bs[kr][cc + 2] = f2tf32(v0.z); Bs[kr][cc + 3] = f2tf32(v0.w);
            Bs[kr][cc + 4] = f2tf32(v1.x); Bs[kr][cc + 5] = f2tf32(v1.y);
            Bs[kr][cc + 6] = f2tf32(v1.z); Bs[kr][cc + 7] = f2tf32(v1.w);
        }
        __syncthreads();

        // ---- compute: 4 k-steps of m16n8k8 ----
#pragma unroll
        for (int kk = 0; kk < 32; kk += 8) {
            unsigned a[2][4], b[4][2];
#pragma unroll
            for (int mt = 0; mt < 2; mt++) {
                const int mr = wm + mt * 16 + qr;
                a[mt][0] = __float_as_uint(As[kk + qc    ][mr    ]);
                a[mt][1] = __float_as_uint(As[kk + qc    ][mr + 8]);
                a[mt][2] = __float_as_uint(As[kk + qc + 4][mr    ]);
                a[mt][3] = __float_as_uint(As[kk + qc + 4][mr + 8]);
            }
#pragma unroll
            for (int nt = 0; nt < 4; nt++) {
                const int nc = wn + nt * 8 + qr;
                b[nt][0] = __float_as_uint(Bs[kk + qc    ][nc]);
                b[nt][1] = __float_as_uint(Bs[kk + qc + 4][nc]);
            }
#pragma unroll
            for (int mt = 0; mt < 2; mt++)
#pragma unroll
                for (int nt = 0; nt < 4; nt++) {
                    asm volatile(
                        "mma.sync.aligned.m16n8k8.row.col.f32.tf32.tf32.f32 "
                        "{%0,%1,%2,%3}, {%4,%5,%6,%7}, {%8,%9}, {%0,%1,%2,%3};"
                        : "+f"(acc[mt][nt][0]), "+f"(acc[mt][nt][1]),
                          "+f"(acc[mt][nt][2]), "+f"(acc[mt][nt][3])
                        : "r"(a[mt][0]), "r"(a[mt][1]), "r"(a[mt][2]), "r"(a[mt][3]),
                          "r"(b[nt][0]), "r"(b[nt][1]));
                }
        }
        __syncthreads();
    }

    // ---- epilogue ----
#pragma unroll
    for (int mt = 0; mt < 2; mt++) {
#pragma unroll
        for (int nt = 0; nt < 4; nt++) {
            const int col = bn + wn + nt * 8 + 2 * qc;
#pragma unroll
            for (int half = 0; half < 2; half++) {
                const int row = bm + wm + mt * 16 + qr + half * 8;
                float v0 = acc[mt][nt][half * 2 + 0] * alpha;
                float v1 = acc[mt][nt][half * 2 + 1] * alpha;
                if (ATOMIC) {
                    atomicAdd(&C[(size_t)row * ldc + col    ], v0);
                    atomicAdd(&C[(size_t)row * ldc + col + 1], v1);
                } else {
                    if (bias) { v0 += bias[col]; v1 += bias[col + 1]; }
                    if (res) {
                        const float2 rv = *(const float2*)(res + (size_t)row * ldr + col);
                        v0 += rv.x; v1 += rv.y;
                    }
                    if (relu) { v0 = fmaxf(v0, 0.f); v1 = fmaxf(v1, 0.f); }
                    float2 o; o.x = v0; o.y = v1;
                    *(float2*)(C + (size_t)row * ldc + col) = o;
                }
            }
        }
    }
}

// ---------------- softmax over 4096-wide rows ----------------
__global__ __launch_bounds__(256)
void softmax_rows(float* __restrict__ S)
{
    __shared__ float buf[4096];
    __shared__ float red[256];
    const int t = threadIdx.x;
    float* p = S + (size_t)blockIdx.x * 4096;

    float m = -3.4e38f;
#pragma unroll
    for (int i = 0; i < 4; i++) {
        const int c = t * 4 + i * 1024;
        float4 v = *(const float4*)(p + c);
        *(float4*)(buf + c) = v;
        m = fmaxf(m, fmaxf(fmaxf(v.x, v.y), fmaxf(v.z, v.w)));
    }
    red[t] = m;
    __syncthreads();
    for (int s = 128; s > 0; s >>= 1) {
        if (t < s) red[t] = fmaxf(red[t], red[t + s]);
        __syncthreads();
    }
    const float M = red[0];
    __syncthreads();

    float sum = 0.f;
#pragma unroll
    for (int i = 0; i < 4; i++) {
        const int c = t * 4 + i * 1024;
        float4 v = *(float4*)(buf + c);
        v.x = __expf(v.x - M); v.y = __expf(v.y - M);
        v.z = __expf(v.z - M); v.w = __expf(v.w - M);
        *(float4*)(buf + c) = v;
        sum += v.x + v.y + v.z + v.w;
    }
    red[t] = sum;
    __syncthreads();
    for (int s = 128; s > 0; s >>= 1) {
        if (t < s) red[t] += red[t + s];
        __syncthreads();
    }
    const float inv = 1.f / red[0];

#pragma unroll
    for (int i = 0; i < 4; i++) {
        const int c = t * 4 + i * 1024;
        float4 v = *(float4*)(buf + c);
        v.x *= inv; v.y *= inv; v.z *= inv; v.w *= inv;
        *(float4*)(p + c) = v;
    }
}

// ---------------- GCN helpers ----------------
__global__ void deg_init_k()
{
    g_deg[blockIdx.x * 256 + threadIdx.x] = 1.0f;
}
__global__ void deg_count_k(const int* __restrict__ ei)
{
    const int e = blockIdx.x * 256 + threadIdx.x;
    atomicAdd(&g_deg[__ldg(ei + NEDGES + e)], 1.0f);
}
__global__ void dinv_k()
{
    const int i = blockIdx.x * 256 + threadIdx.x;
    g_dinv[i] = rsqrtf(g_deg[i]);
}
__global__ void agg_init_k()
{
    const int idx = blockIdx.x * 256 + threadIdx.x;
    const int i = idx >> 8;
    const float dv = g_dinv[i];
    g_agg[idx] = dv * dv * g_xw[idx];
}
__global__ void gcn_scatter_k(const int* __restrict__ ei)
{
    const int gid  = blockIdx.x * 256 + threadIdx.x;
    const int e    = gid >> 5;
    const int lane = gid & 31;
    const int s = __ldg(ei + e);
    const int d = __ldg(ei + NEDGES + e);
    const float coef = g_dinv[s] * g_dinv[d];
    const float* xs = g_xw + (size_t)s * HD;
    float* ad = g_agg + (size_t)d * HD;
#pragma unroll
    for (int c = lane; c < HD; c += 32)
        atomicAdd(&ad[c], coef * xs[c]);
}
__global__ void add_bias_2x_k(const float* __restrict__ b)
{
    const int idx = blockIdx.x * 256 + threadIdx.x;
    g_agg[idx] += b[idx & 255] + 2.0f * g_h[idx];
}
__global__ void zero_attn_k()
{
    g_attn[blockIdx.x * 256 + threadIdx.x] = 0.f;
}

// ---------------- final symmetrization in place ----------------
__global__ __launch_bounds__(1024)
void symmetrize_k(float* __restrict__ D)
{
    if (blockIdx.x < blockIdx.y) return;
    if (blockIdx.x == blockIdx.y && threadIdx.x < threadIdx.y) return;
    const int i = blockIdx.y * 32 + threadIdx.y;
    const int j = blockIdx.x * 32 + threadIdx.x;
    const float a = D[(size_t)i * 4096 + j];
    const float b = D[(size_t)j * 4096 + i];
    const float v = 0.5f * (a + b);
    D[(size_t)i * 4096 + j] = v;
    D[(size_t)j * 4096 + i] = v;
}

// ---------------- host-side helpers ----------------
static inline void gemmNT(const float* A, int lda, const float* B, int ldb,
                          float* C, int ldc, int M, int N, int K, float alpha,
                          const float* bias, const float* res, int ldr, int relu)
{
    dim3 grid(N / 64, M / 128, 1);
    gemm_tc<true, false><<<grid, 256>>>(A, lda, B, ldb, C, ldc, K, alpha, bias, res, ldr, relu);
}
static inline void gemmNN_split(const float* A, int lda, const float* B, int ldb,
                                float* C, int ldc, int M, int N, int K, int split)
{
    dim3 grid(N / 64, M / 128, split);
    gemm_tc<false, true><<<grid, 256>>>(A, lda, B, ldb, C, ldc, K / split, 1.f,
                                        nullptr, nullptr, 0, 0);
}

extern "C" void kernel_launch(void* const* d_in, const int* in_sizes, int n_in,
                              void* d_out, int out_size)
{
    const float* x     = (const float*)d_in[0];
    const int*   ei    = (const int*)  d_in[1];
    const float* pre_w = (const float*)d_in[2];
    const float* pre_b = (const float*)d_in[3];
    const float* P[2][10];
    for (int g = 0; g < 2; g++)
        for (int k = 0; k < 10; k++)
            P[g][k] = (const float*)d_in[4 + g * 10 + k];
    const float* mlp_w1 = (const float*)d_in[24];
    const float* mlp_b1 = (const float*)d_in[25];
    const float* mlp_w2 = (const float*)d_in[26];
    const float* mlp_b2 = (const float*)d_in[27];
    float* out = (float*)d_out;

    float *h, *xw, *agg, *qkv, *attn, *outb, *ffn, *z;
    cudaGetSymbolAddress((void**)&h,    g_h);
    cudaGetSymbolAddress((void**)&xw,   g_xw);
    cudaGetSymbolAddress((void**)&agg,  g_agg);
    cudaGetSymbolAddress((void**)&qkv,  g_qkv);
    cudaGetSymbolAddress((void**)&attn, g_attn);
    cudaGetSymbolAddress((void**)&outb, g_out);
    cudaGetSymbolAddress((void**)&ffn,  g_ffn);
    cudaGetSymbolAddress((void**)&z,    g_z);

    // pre: h = relu(x @ pre_w^T + pre_b)
    gemmNT(x, 128, pre_w, 128, h, HD, NNODES, HD, 128, 1.f, pre_b, nullptr, 0, 1);

    // degrees (same for both GPS blocks)
    deg_init_k<<<NNODES / 256, 256>>>();
    deg_count_k<<<NEDGES / 256, 256>>>(ei);
    dinv_k<<<NNODES / 256, 256>>>();

    for (int g = 0; g < 2; g++) {
        const float* gcn_w = P[g][0]; const float* gcn_b = P[g][1];
        const float* in_w  = P[g][2]; const float* in_b  = P[g][3];
        const float* out_w = P[g][4]; const float* out_b = P[g][5];
        const float* w1    = P[g][6]; const float* b1    = P[g][7];
        const float* w2    = P[g][8]; const float* b2    = P[g][9];

        // GCN: xw = h @ gcn_w^T ; normalized aggregation into agg
        gemmNT(h, HD, gcn_w, HD, xw, HD, NNODES, HD, HD, 1.f, nullptr, nullptr, 0, 0);
        agg_init_k<<<NNODES * HD / 256, 256>>>();
        gcn_scatter_k<<<NEDGES * 32 / 256, 256>>>(ei);
        add_bias_2x_k<<<NNODES * HD / 256, 256>>>(gcn_b);   // agg = gcn-out + gcn_b + 2h

        // attention: qkv = h @ in_w^T + in_b
        gemmNT(h, HD, in_w, HD, qkv, 3 * HD, NNODES, 3 * HD, HD, 1.f, in_b, nullptr, 0, 0);

        zero_attn_k<<<NNODES * HD / 256, 256>>>();
        for (int hd = 0; hd < 4; hd++) {
            // S = (q * d^-1/2) @ k^T  -> scratch in d_out
            gemmNT(qkv + hd * 64, 3 * HD, qkv + HD + hd * 64, 3 * HD,
                   out, 4096, NNODES, NNODES, 64, 0.125f, nullptr, nullptr, 0, 0);
            softmax_rows<<<NNODES, 256>>>(out);
            // O_head = S @ v  (NN, split-K=8, atomic accumulate)
            gemmNN_split(out, 4096, qkv + 2 * HD + hd * 64, 3 * HD,
                         attn + hd * 64, HD, NNODES, 64, NNODES, 8);
        }

        // out = attn @ out_w^T + out_b + agg   [agg holds h1 + 2h]
        gemmNT(attn, HD, out_w, HD, outb, HD, NNODES, HD, HD, 1.f, out_b, agg, HD, 0);

        // FFN + residual + outer relu -> h
        gemmNT(outb, HD, w1, HD, ffn, 2 * HD, NNODES, 2 * HD, HD, 1.f, b1, nullptr, 0, 1);
        gemmNT(ffn, 2 * HD, w2, 2 * HD, h, HD, NNODES, HD, 2 * HD, 1.f, b2, outb, HD, 1);
    }

    // final: z = relu(h @ mlp_w1^T + b1); delta = z @ mlp_w2^T + b2; sym in-place
    gemmNT(h, HD, mlp_w1, HD, z, HD, NNODES, HD, HD, 1.f, mlp_b1, nullptr, 0, 1);
    gemmNT(z, HD, mlp_w2, HD, out, 4096, NNODES, 4096, HD, 1.f, mlp_b2, nullptr, 0, 0);
    symmetrize_k<<<dim3(128, 128), dim3(32, 32)>>>(out);
}

// round 5
// speedup vs baseline: 2.9411x; 1.1489x over previous
#include <cuda_runtime.h>
#include <math.h>

#define NNODES 4096
#define NEDGES 65536
#define HD     256

// ---------------- scratch (static device memory; no allocs allowed) ----------------
__device__ float g_h   [NNODES * HD];
__device__ float g_xw  [NNODES * HD];
__device__ float g_agg [NNODES * HD];
__device__ float g_qkv [NNODES * 3 * HD];
__device__ float g_attn[NNODES * HD];
__device__ float g_out [NNODES * HD];
__device__ float g_ffn [NNODES * 2 * HD];
__device__ float g_z   [NNODES * HD];
__device__ float g_dinv[NNODES];
__device__ float g_deg [NNODES];

__device__ __forceinline__ float f2tf32(float x)
{
    asm("cvt.rna.tf32.f32 %0, %1;" : "=f"(x) : "f"(x));
    return x;
}

__device__ __forceinline__ void mma_tf32(float* c, const unsigned* a, const unsigned* b)
{
    asm volatile(
        "mma.sync.aligned.m16n8k8.row.col.f32.tf32.tf32.f32 "
        "{%0,%1,%2,%3}, {%4,%5,%6,%7}, {%8,%9}, {%0,%1,%2,%3};"
        : "+f"(c[0]), "+f"(c[1]), "+f"(c[2]), "+f"(c[3])
        : "r"(a[0]), "r"(a[1]), "r"(a[2]), "r"(a[3]), "r"(b[0]), "r"(b[1]));
}

// ---------------- tf32 tensor-core GEMM (NT: B is [N,K] weights) ----------------
// C[M,N] = relu?( alpha * A @ B^T + bias + res )
// BM=128, BN=64, BK=32. 256 threads = 8 warps (4 x 2), warp tile 32x32.
__global__ __launch_bounds__(256)
void gemm_tc(const float* __restrict__ A, int lda,
             const float* __restrict__ B, int ldb,
             float* __restrict__ C, int ldc,
             int K, float alpha,
             const float* __restrict__ bias,
             const float* __restrict__ res, int ldr,
             int relu)
{
    __shared__ float As[32][136];
    __shared__ float Bs[32][72];

    const int bm = blockIdx.y * 128;
    const int bn = blockIdx.x * 64;
    const int t  = threadIdx.x;
    const int w  = t >> 5;
    const int lane = t & 31;
    const int qr = lane >> 2;
    const int qc = lane & 3;
    const int wm = (w & 3) * 32;
    const int wn = (w >> 2) * 32;

    float acc[2][4][4];
#pragma unroll
    for (int i = 0; i < 2; i++)
#pragma unroll
        for (int j = 0; j < 4; j++)
#pragma unroll
            for (int r = 0; r < 4; r++) acc[i][j][r] = 0.f;

    for (int k0 = 0; k0 < K; k0 += 32) {
        {
            const int r  = t >> 1;
            const int ch = (t & 1) * 16;
            const float* ap = A + (size_t)(bm + r) * lda + k0 + ch;
#pragma unroll
            for (int q = 0; q < 4; q++) {
                float4 v = *(const float4*)(ap + q * 4);
                As[ch + q * 4 + 0][r] = f2tf32(v.x);
                As[ch + q * 4 + 1][r] = f2tf32(v.y);
                As[ch + q * 4 + 2][r] = f2tf32(v.z);
                As[ch + q * 4 + 3][r] = f2tf32(v.w);
            }
        }
        {
            const int r  = t >> 2;
            const int ch = (t & 3) * 8;
            const float* bp = B + (size_t)(bn + r) * ldb + k0 + ch;
            float4 v0 = *(const float4*)(bp);
            float4 v1 = *(const float4*)(bp + 4);
            Bs[ch + 0][r] = f2tf32(v0.x); Bs[ch + 1][r] = f2tf32(v0.y);
            Bs[ch + 2][r] = f2tf32(v0.z); Bs[ch + 3][r] = f2tf32(v0.w);
            Bs[ch + 4][r] = f2tf32(v1.x); Bs[ch + 5][r] = f2tf32(v1.y);
            Bs[ch + 6][r] = f2tf32(v1.z); Bs[ch + 7][r] = f2tf32(v1.w);
        }
        __syncthreads();

#pragma unroll
        for (int kk = 0; kk < 32; kk += 8) {
            unsigned a[2][4], b[4][2];
#pragma unroll
            for (int mt = 0; mt < 2; mt++) {
                const int mr = wm + mt * 16 + qr;
                a[mt][0] = __float_as_uint(As[kk + qc    ][mr    ]);
                a[mt][1] = __float_as_uint(As[kk + qc    ][mr + 8]);
                a[mt][2] = __float_as_uint(As[kk + qc + 4][mr    ]);
                a[mt][3] = __float_as_uint(As[kk + qc + 4][mr + 8]);
            }
#pragma unroll
            for (int nt = 0; nt < 4; nt++) {
                const int nc = wn + nt * 8 + qr;
                b[nt][0] = __float_as_uint(Bs[kk + qc    ][nc]);
                b[nt][1] = __float_as_uint(Bs[kk + qc + 4][nc]);
            }
#pragma unroll
            for (int mt = 0; mt < 2; mt++)
#pragma unroll
                for (int nt = 0; nt < 4; nt++)
                    mma_tf32(acc[mt][nt], a[mt], b[nt]);
        }
        __syncthreads();
    }

#pragma unroll
    for (int mt = 0; mt < 2; mt++) {
#pragma unroll
        for (int nt = 0; nt < 4; nt++) {
            const int col = bn + wn + nt * 8 + 2 * qc;
#pragma unroll
            for (int half = 0; half < 2; half++) {
                const int row = bm + wm + mt * 16 + qr + half * 8;
                float v0 = acc[mt][nt][half * 2 + 0] * alpha;
                float v1 = acc[mt][nt][half * 2 + 1] * alpha;
                if (bias) { v0 += bias[col]; v1 += bias[col + 1]; }
                if (res) {
                    const float2 rv = *(const float2*)(res + (size_t)row * ldr + col);
                    v0 += rv.x; v1 += rv.y;
                }
                if (relu) { v0 = fmaxf(v0, 0.f); v1 = fmaxf(v1, 0.f); }
                float2 o; o.x = v0; o.y = v1;
                *(float2*)(C + (size_t)row * ldc + col) = o;
            }
        }
    }
}

// ---------------- fused flash attention (one layer, all 4 heads) ----------------
// grid: (64 qblocks, 4 heads), 128 threads = 4 warps, each warp owns 16 query rows.
// Q/K/V at qkv + {0,256,512} + head*64, row stride 768. Output: attn + head*64, stride 256.
#define FA_SQ  0                 // sQ  [64][72]  (k-major: sQ[k*72 + m])
#define FA_SK  (64 * 72)         // sK  [64][72]  (sK[feat*72 + key])
#define FA_SV  (2 * 64 * 72)     // sV  [64][72]  (sV[key*72 + feat])
#define FA_SP  (3 * 64 * 72)     // sP  [4][64][24]  per-warp [key*24 + qrow]
#define FA_SMEM ((3 * 64 * 72 + 4 * 64 * 24) * 4)

__global__ __launch_bounds__(128)
void flash_attn_k(const float* __restrict__ qkv, float* __restrict__ attn)
{
    extern __shared__ float sm[];
    float* sQ = sm + FA_SQ;
    float* sK = sm + FA_SK;
    float* sV = sm + FA_SV;

    const int head  = blockIdx.y;
    const int qbase = blockIdx.x * 64;
    const int t     = threadIdx.x;
    const int w     = t >> 5;
    const int lane  = t & 31;
    const int qr    = lane >> 2;
    const int qc    = lane & 3;
    float* pw = sm + FA_SP + w * 64 * 24;

    const float* Q = qkv + head * 64;
    const float* K = qkv + 256 + head * 64;
    const float* V = qkv + 512 + head * 64;

    // load Q tile (scaled, tf32-rounded), transposed into sQ[k][m]
    {
        const int r  = t >> 1;
        const int c0 = (t & 1) * 32;
        const float* qp = Q + (size_t)(qbase + r) * 768 + c0;
#pragma unroll
        for (int q = 0; q < 8; q++) {
            float4 v = *(const float4*)(qp + q * 4);
            const int c = c0 + q * 4;
            sQ[(c + 0) * 72 + r] = f2tf32(v.x * 0.125f);
            sQ[(c + 1) * 72 + r] = f2tf32(v.y * 0.125f);
            sQ[(c + 2) * 72 + r] = f2tf32(v.z * 0.125f);
            sQ[(c + 3) * 72 + r] = f2tf32(v.w * 0.125f);
        }
    }

    float m0 = -3.4e38f, m1 = -3.4e38f;
    float l0 = 0.f, l1 = 0.f;
    float o[8][4];
#pragma unroll
    for (int nt = 0; nt < 8; nt++)
#pragma unroll
        for (int r = 0; r < 4; r++) o[nt][r] = 0.f;

    for (int kb = 0; kb < 64; kb++) {
        __syncthreads();
        // load K chunk transposed: sK[feat][key]
        {
            const int r  = t >> 1;                      // key within chunk
            const int c0 = (t & 1) * 32;
            const float* kp = K + (size_t)(kb * 64 + r) * 768 + c0;
#pragma unroll
            for (int q = 0; q < 8; q++) {
                float4 v = *(const float4*)(kp + q * 4);
                const int c = c0 + q * 4;
                sK[(c + 0) * 72 + r] = f2tf32(v.x);
                sK[(c + 1) * 72 + r] = f2tf32(v.y);
                sK[(c + 2) * 72 + r] = f2tf32(v.z);
                sK[(c + 3) * 72 + r] = f2tf32(v.w);
            }
        }
        // load V chunk direct: sV[key][feat]
        {
            const int r  = t >> 1;
            const int c0 = (t & 1) * 32;
            const float* vp = V + (size_t)(kb * 64 + r) * 768 + c0;
#pragma unroll
            for (int q = 0; q < 8; q++) {
                float4 v = *(const float4*)(vp + q * 4);
                v.x = f2tf32(v.x); v.y = f2tf32(v.y);
                v.z = f2tf32(v.z); v.w = f2tf32(v.w);
                *(float4*)(sV + r * 72 + c0 + q * 4) = v;
            }
        }
        __syncthreads();

        // ---- S = Qtile @ Kchunk^T  (16 x 64 per warp) ----
        float s[8][4];
#pragma unroll
        for (int nt = 0; nt < 8; nt++)
#pragma unroll
            for (int r = 0; r < 4; r++) s[nt][r] = 0.f;

#pragma unroll
        for (int kk = 0; kk < 64; kk += 8) {
            unsigned a[4];
            const int mr = w * 16 + qr;
            a[0] = __float_as_uint(sQ[(kk + qc    ) * 72 + mr    ]);
            a[1] = __float_as_uint(sQ[(kk + qc    ) * 72 + mr + 8]);
            a[2] = __float_as_uint(sQ[(kk + qc + 4) * 72 + mr    ]);
            a[3] = __float_as_uint(sQ[(kk + qc + 4) * 72 + mr + 8]);
#pragma unroll
            for (int nt = 0; nt < 8; nt++) {
                unsigned b[2];
                b[0] = __float_as_uint(sK[(kk + qc    ) * 72 + nt * 8 + qr]);
                b[1] = __float_as_uint(sK[(kk + qc + 4) * 72 + nt * 8 + qr]);
                mma_tf32(s[nt], a, b);
            }
        }

        // ---- online softmax ----
        float cm0 = -3.4e38f, cm1 = -3.4e38f;
#pragma unroll
        for (int nt = 0; nt < 8; nt++) {
            cm0 = fmaxf(cm0, fmaxf(s[nt][0], s[nt][1]));
            cm1 = fmaxf(cm1, fmaxf(s[nt][2], s[nt][3]));
        }
        cm0 = fmaxf(cm0, __shfl_xor_sync(0xffffffff, cm0, 1));
        cm0 = fmaxf(cm0, __shfl_xor_sync(0xffffffff, cm0, 2));
        cm1 = fmaxf(cm1, __shfl_xor_sync(0xffffffff, cm1, 1));
        cm1 = fmaxf(cm1, __shfl_xor_sync(0xffffffff, cm1, 2));

        const float nm0 = fmaxf(m0, cm0);
        const float nm1 = fmaxf(m1, cm1);
        const float sc0 = __expf(m0 - nm0);
        const float sc1 = __expf(m1 - nm1);
        m0 = nm0; m1 = nm1;

        float rs0 = 0.f, rs1 = 0.f;
#pragma unroll
        for (int nt = 0; nt < 8; nt++) {
            s[nt][0] = __expf(s[nt][0] - nm0);
            s[nt][1] = __expf(s[nt][1] - nm0);
            s[nt][2] = __expf(s[nt][2] - nm1);
            s[nt][3] = __expf(s[nt][3] - nm1);
            rs0 += s[nt][0] + s[nt][1];
            rs1 += s[nt][2] + s[nt][3];
        }
        rs0 += __shfl_xor_sync(0xffffffff, rs0, 1);
        rs0 += __shfl_xor_sync(0xffffffff, rs0, 2);
        rs1 += __shfl_xor_sync(0xffffffff, rs1, 1);
        rs1 += __shfl_xor_sync(0xffffffff, rs1, 2);
        l0 = l0 * sc0 + rs0;
        l1 = l1 * sc1 + rs1;

        // rescale O, stash P into per-warp smem
#pragma unroll
        for (int nt = 0; nt < 8; nt++) {
            o[nt][0] *= sc0; o[nt][1] *= sc0;
            o[nt][2] *= sc1; o[nt][3] *= sc1;
            const int c0 = nt * 8 + 2 * qc;
            pw[(c0    ) * 24 + qr    ] = f2tf32(s[nt][0]);
            pw[(c0 + 1) * 24 + qr    ] = f2tf32(s[nt][1]);
            pw[(c0    ) * 24 + qr + 8] = f2tf32(s[nt][2]);
            pw[(c0 + 1) * 24 + qr + 8] = f2tf32(s[nt][3]);
        }
        __syncwarp();

        // ---- O += P @ Vchunk ----
#pragma unroll
        for (int kk = 0; kk < 64; kk += 8) {
            unsigned a[4];
            a[0] = __float_as_uint(pw[(kk + qc    ) * 24 + qr    ]);
            a[1] = __float_as_uint(pw[(kk + qc    ) * 24 + qr + 8]);
            a[2] = __float_as_uint(pw[(kk + qc + 4) * 24 + qr    ]);
            a[3] = __float_as_uint(pw[(kk + qc + 4) * 24 + qr + 8]);
#pragma unroll
            for (int nt = 0; nt < 8; nt++) {
                unsigned b[2];
                b[0] = __float_as_uint(sV[(kk + qc    ) * 72 + nt * 8 + qr]);
                b[1] = __float_as_uint(sV[(kk + qc + 4) * 72 + nt * 8 + qr]);
                mma_tf32(o[nt], a, b);
            }
        }
        __syncwarp();
    }

    // epilogue: divide by row sums, write
    const float inv0 = 1.f / l0;
    const float inv1 = 1.f / l1;
    const int row0 = qbase + w * 16 + qr;
    const int row1 = row0 + 8;
#pragma unroll
    for (int nt = 0; nt < 8; nt++) {
        const int col = head * 64 + nt * 8 + 2 * qc;
        float2 v0; v0.x = o[nt][0] * inv0; v0.y = o[nt][1] * inv0;
        float2 v1; v1.x = o[nt][2] * inv1; v1.y = o[nt][3] * inv1;
        *(float2*)(attn + (size_t)row0 * 256 + col) = v0;
        *(float2*)(attn + (size_t)row1 * 256 + col) = v1;
    }
}

// ---------------- GCN helpers ----------------
__global__ void deg_init_k()
{
    g_deg[blockIdx.x * 256 + threadIdx.x] = 1.0f;
}
__global__ void deg_count_k(const int* __restrict__ ei)
{
    const int e = blockIdx.x * 256 + threadIdx.x;
    atomicAdd(&g_deg[__ldg(ei + NEDGES + e)], 1.0f);
}
__global__ void dinv_k()
{
    const int i = blockIdx.x * 256 + threadIdx.x;
    g_dinv[i] = rsqrtf(g_deg[i]);
}
__global__ void agg_init_k()
{
    const int idx = blockIdx.x * 256 + threadIdx.x;
    const int i = idx >> 8;
    const float dv = g_dinv[i];
    g_agg[idx] = dv * dv * g_xw[idx];
}
__global__ void gcn_scatter_k(const int* __restrict__ ei)
{
    const int gid  = blockIdx.x * 256 + threadIdx.x;
    const int e    = gid >> 5;
    const int lane = gid & 31;
    const int s = __ldg(ei + e);
    const int d = __ldg(ei + NEDGES + e);
    const float coef = g_dinv[s] * g_dinv[d];
    const float* xs = g_xw + (size_t)s * HD;
    float* ad = g_agg + (size_t)d * HD;
#pragma unroll
    for (int c = lane; c < HD; c += 32)
        atomicAdd(&ad[c], coef * xs[c]);
}
__global__ void add_bias_2x_k(const float* __restrict__ b)
{
    const int idx = blockIdx.x * 256 + threadIdx.x;
    g_agg[idx] += b[idx & 255] + 2.0f * g_h[idx];
}

// ---------------- final symmetrization in place ----------------
__global__ __launch_bounds__(1024)
void symmetrize_k(float* __restrict__ D)
{
    if (blockIdx.x < blockIdx.y) return;
    if (blockIdx.x == blockIdx.y && threadIdx.x < threadIdx.y) return;
    const int i = blockIdx.y * 32 + threadIdx.y;
    const int j = blockIdx.x * 32 + threadIdx.x;
    const float a = D[(size_t)i * 4096 + j];
    const float b = D[(size_t)j * 4096 + i];
    const float v = 0.5f * (a + b);
    D[(size_t)i * 4096 + j] = v;
    D[(size_t)j * 4096 + i] = v;
}

// ---------------- host-side helper ----------------
static inline void gemmNT(const float* A, int lda, const float* B, int ldb,
                          float* C, int ldc, int M, int N, int K, float alpha,
                          const float* bias, const float* res, int ldr, int relu)
{
    dim3 grid(N / 64, M / 128, 1);
    gemm_tc<<<grid, 256>>>(A, lda, B, ldb, C, ldc, K, alpha, bias, res, ldr, relu);
}

extern "C" void kernel_launch(void* const* d_in, const int* in_sizes, int n_in,
                              void* d_out, int out_size)
{
    const float* x     = (const float*)d_in[0];
    const int*   ei    = (const int*)  d_in[1];
    const float* pre_w = (const float*)d_in[2];
    const float* pre_b = (const float*)d_in[3];
    const float* P[2][10];
    for (int g = 0; g < 2; g++)
        for (int k = 0; k < 10; k++)
            P[g][k] = (const float*)d_in[4 + g * 10 + k];
    const float* mlp_w1 = (const float*)d_in[24];
    const float* mlp_b1 = (const float*)d_in[25];
    const float* mlp_w2 = (const float*)d_in[26];
    const float* mlp_b2 = (const float*)d_in[27];
    float* out = (float*)d_out;

    float *h, *xw, *agg, *qkv, *attn, *outb, *ffn, *z;
    cudaGetSymbolAddress((void**)&h,    g_h);
    cudaGetSymbolAddress((void**)&xw,   g_xw);
    cudaGetSymbolAddress((void**)&agg,  g_agg);
    cudaGetSymbolAddress((void**)&qkv,  g_qkv);
    cudaGetSymbolAddress((void**)&attn, g_attn);
    cudaGetSymbolAddress((void**)&outb, g_out);
    cudaGetSymbolAddress((void**)&ffn,  g_ffn);
    cudaGetSymbolAddress((void**)&z,    g_z);

    cudaFuncSetAttribute(flash_attn_k, cudaFuncAttributeMaxDynamicSharedMemorySize, FA_SMEM);

    // pre: h = relu(x @ pre_w^T + pre_b)
    gemmNT(x, 128, pre_w, 128, h, HD, NNODES, HD, 128, 1.f, pre_b, nullptr, 0, 1);

    // degrees (same for both GPS blocks)
    deg_init_k<<<NNODES / 256, 256>>>();
    deg_count_k<<<NEDGES / 256, 256>>>(ei);
    dinv_k<<<NNODES / 256, 256>>>();

    for (int g = 0; g < 2; g++) {
        const float* gcn_w = P[g][0]; const float* gcn_b = P[g][1];
        const float* in_w  = P[g][2]; const float* in_b  = P[g][3];
        const float* out_w = P[g][4]; const float* out_b = P[g][5];
        const float* w1    = P[g][6]; const float* b1    = P[g][7];
        const float* w2    = P[g][8]; const float* b2    = P[g][9];

        // GCN: xw = h @ gcn_w^T ; normalized aggregation into agg
        gemmNT(h, HD, gcn_w, HD, xw, HD, NNODES, HD, HD, 1.f, nullptr, nullptr, 0, 0);
        agg_init_k<<<NNODES * HD / 256, 256>>>();
        gcn_scatter_k<<<NEDGES * 32 / 256, 256>>>(ei);
        add_bias_2x_k<<<NNODES * HD / 256, 256>>>(gcn_b);   // agg = gcn-out + gcn_b + 2h

        // attention: qkv = h @ in_w^T + in_b
        gemmNT(h, HD, in_w, HD, qkv, 3 * HD, NNODES, 3 * HD, HD, 1.f, in_b, nullptr, 0, 0);

        // fused flash attention (all heads)
        flash_attn_k<<<dim3(64, 4), 128, FA_SMEM>>>(qkv, attn);

        // out = attn @ out_w^T + out_b + agg   [agg holds h1 + 2h]
        gemmNT(attn, HD, out_w, HD, outb, HD, NNODES, HD, HD, 1.f, out_b, agg, HD, 0);

        // FFN + residual + outer relu -> h
        gemmNT(outb, HD, w1, HD, ffn, 2 * HD, NNODES, 2 * HD, HD, 1.f, b1, nullptr, 0, 1);
        gemmNT(ffn, 2 * HD, w2, 2 * HD, h, HD, NNODES, HD, 2 * HD, 1.f, b2, outb, HD, 1);
    }

    // final: z = relu(h @ mlp_w1^T + b1); delta = z @ mlp_w2^T + b2; sym in-place
    gemmNT(h, HD, mlp_w1, HD, z, HD, NNODES, HD, HD, 1.f, mlp_b1, nullptr, 0, 1);
    gemmNT(z, HD, mlp_w2, HD, out, 4096, NNODES, 4096, HD, 1.f, mlp_b2, nullptr, 0, 0);
    symmetrize_k<<<dim3(128, 128), dim3(32, 32)>>>(out);
}